// round 3
// baseline (speedup 1.0000x reference)
#include <cuda_runtime.h>
#include <cstdint>

// ---------------------------------------------------------------------------
// MultiScaleGraphPropagate: out[k] = A^k x for k=0..2, where
//   A[n, src] = mean_l edge_w[b, l, e]  for each edge e = (tgt=n, src)
// applied per (b, t) slice. Output: (3, B, T, N, F) fp32.
//
// CSR-by-target build (per launch, deterministic), then two pure-gather hop
// kernels. One warp per (b, n), lane = f; t-loop reuses edge metadata 8x;
// edge loop unrolled x2 for MLP ~16 per warp.
//
// edge_index dtype is detected on-device (int32 vs int64): JAX with x64
// disabled silently downcasts jnp.int64 -> int32.
// ---------------------------------------------------------------------------

#define Bc 4
#define Tc 8
#define Nc 10000
#define Fc 32
#define Lc 3
#define Ec 160000
#define Sc (Bc * Tc * Nc * Fc)   // 10,240,000 floats per scale slab

// Scratch (device globals; no allocations allowed)
__device__ int   g_is64;
__device__ int   g_counts[Nc];
__device__ int   g_offsets[Nc + 1];
__device__ int   g_cursor[Nc];
__device__ int   g_src[Ec];
__device__ int   g_eid[Ec];
__device__ float g_csrw[Bc * Ec];

// ---------------------------------------------------------------------------
__global__ void init_kernel() {
    int i = blockIdx.x * blockDim.x + threadIdx.x;
    if (i < Nc) g_counts[i] = 0;
    if (i == 0) g_is64 = 1;
}

// Interpret first E 8-byte words as int64; if ANY is outside [0, Nc) the data
// must be int32 (pairs of small ints look huge as int64). E*8 bytes == full
// int32 buffer, so no over-read either way.
__global__ void detect_kernel(const long long* __restrict__ eidx) {
    int i = blockIdx.x * blockDim.x + threadIdx.x;
    if (i < Ec) {
        long long v = eidx[i];
        if (v < 0 || v >= (long long)Nc) atomicAnd(&g_is64, 0);
    }
}

__global__ void count_kernel(const void* __restrict__ eidx_raw) {
    int e = blockIdx.x * blockDim.x + threadIdx.x;
    if (e < Ec) {
        int tgt;
        if (g_is64) tgt = (int)((const long long*)eidx_raw)[e];
        else        tgt = ((const int*)eidx_raw)[e];
        atomicAdd(&g_counts[tgt], 1);
    }
}

// Single-block exclusive scan over g_counts -> g_offsets (N=10000, 1024 thr)
__global__ void scan_kernel() {
    __shared__ int wsum[32];
    const int ITEMS = 10;                  // 1024*10 >= 10000
    int tid  = threadIdx.x;
    int lane = tid & 31, wid = tid >> 5;
    int base = tid * ITEMS;

    int vals[ITEMS];
    int run = 0;
#pragma unroll
    for (int i = 0; i < ITEMS; ++i) {
        int idx = base + i;
        int c = (idx < Nc) ? g_counts[idx] : 0;
        vals[i] = run;
        run += c;
    }
    int inc = run;
#pragma unroll
    for (int off = 1; off < 32; off <<= 1) {
        int v = __shfl_up_sync(0xffffffffu, inc, off);
        if (lane >= off) inc += v;
    }
    if (lane == 31) wsum[wid] = inc;
    __syncthreads();
    if (wid == 0) {
        int v = wsum[lane];
#pragma unroll
        for (int off = 1; off < 32; off <<= 1) {
            int u = __shfl_up_sync(0xffffffffu, v, off);
            if (lane >= off) v += u;
        }
        wsum[lane] = v;                    // inclusive warp totals
    }
    __syncthreads();
    int warp_base = (wid > 0) ? wsum[wid - 1] : 0;
    int texcl = warp_base + (inc - run);
#pragma unroll
    for (int i = 0; i < ITEMS; ++i) {
        int idx = base + i;
        if (idx < Nc) g_offsets[idx] = texcl + vals[i];
    }
    if (tid == 0) g_offsets[Nc] = Ec;
}

__global__ void init_cursor_kernel() {
    int i = blockIdx.x * blockDim.x + threadIdx.x;
    if (i < Nc) g_cursor[i] = g_offsets[i];
}

__global__ void fill_kernel(const void* __restrict__ eidx_raw) {
    int e = blockIdx.x * blockDim.x + threadIdx.x;
    if (e < Ec) {
        int tgt, src;
        if (g_is64) {
            tgt = (int)((const long long*)eidx_raw)[e];
            src = (int)((const long long*)eidx_raw)[Ec + e];
        } else {
            tgt = ((const int*)eidx_raw)[e];
            src = ((const int*)eidx_raw)[Ec + e];
        }
        int pos = atomicAdd(&g_cursor[tgt], 1);
        g_src[pos] = src;
        g_eid[pos] = e;
    }
}

// Fused: mean over L and permute into CSR order. csr_w[b][pos]
__global__ void permute_w_kernel(const float* __restrict__ edge_w) {
    int idx = blockIdx.x * blockDim.x + threadIdx.x;   // over B*E
    if (idx < Bc * Ec) {
        int b   = idx / Ec;
        int pos = idx - b * Ec;
        int e   = g_eid[pos];
        const float* ew = edge_w + (size_t)b * (Lc * Ec) + e;
        float m = (ew[0] + ew[Ec] + ew[2 * Ec]) * (1.0f / 3.0f);
        g_csrw[idx] = m;
    }
}

// out[0] = x  (float4 copy)
__global__ void copy_kernel(const float4* __restrict__ in, float4* __restrict__ out) {
    int i = blockIdx.x * blockDim.x + threadIdx.x;
    if (i < Sc / 4) out[i] = in[i];
}

// One warp per (b, n); lane = f. Gathers deg(n) edges, 8 t-slices each.
// Edge loop unrolled x2 -> up to 16 outstanding loads per warp.
__global__ __launch_bounds__(256) void hop_kernel(const float* __restrict__ in,
                                                  float* __restrict__ out) {
    int w    = (blockIdx.x * blockDim.x + threadIdx.x) >> 5;
    int lane = threadIdx.x & 31;
    if (w >= Bc * Nc) return;
    int b = w / Nc;
    int n = w - b * Nc;

    int beg = g_offsets[n];
    int end = g_offsets[n + 1];

    float acc[Tc];
#pragma unroll
    for (int t = 0; t < Tc; ++t) acc[t] = 0.0f;

    const float* __restrict__ wrow = g_csrw + b * Ec;
    const float* __restrict__ inb  = in + (unsigned)b * (Tc * Nc * Fc) + lane;

    int pos = beg;
    for (; pos + 2 <= end; pos += 2) {
        int   src0 = g_src[pos];
        int   src1 = g_src[pos + 1];
        float wv0  = wrow[pos];
        float wv1  = wrow[pos + 1];
        const float* p0 = inb + (unsigned)src0 * Fc;
        const float* p1 = inb + (unsigned)src1 * Fc;
        float v0[Tc], v1[Tc];
#pragma unroll
        for (int t = 0; t < Tc; ++t) v0[t] = __ldg(p0 + (unsigned)t * (Nc * Fc));
#pragma unroll
        for (int t = 0; t < Tc; ++t) v1[t] = __ldg(p1 + (unsigned)t * (Nc * Fc));
#pragma unroll
        for (int t = 0; t < Tc; ++t) acc[t] = fmaf(wv0, v0[t], acc[t]);
#pragma unroll
        for (int t = 0; t < Tc; ++t) acc[t] = fmaf(wv1, v1[t], acc[t]);
    }
    if (pos < end) {
        int   src = g_src[pos];
        float wv  = wrow[pos];
        const float* p = inb + (unsigned)src * Fc;
#pragma unroll
        for (int t = 0; t < Tc; ++t)
            acc[t] = fmaf(wv, __ldg(p + (unsigned)t * (Nc * Fc)), acc[t]);
    }

    float* ob = out + ((unsigned)b * (Tc * Nc) + (unsigned)n) * Fc + lane;
#pragma unroll
    for (int t = 0; t < Tc; ++t)
        ob[(unsigned)t * (Nc * Fc)] = acc[t];
}

// ---------------------------------------------------------------------------
extern "C" void kernel_launch(void* const* d_in, const int* in_sizes, int n_in,
                              void* d_out, int out_size) {
    const float* x      = (const float*)d_in[0];
    const float* edge_w = (const float*)d_in[1];
    const void*  eidx   = d_in[2];
    float*       out    = (float*)d_out;

    (void)in_sizes; (void)n_in; (void)out_size;

    // CSR build (with on-device dtype detection for edge_index)
    init_kernel<<<(Nc + 255) / 256, 256>>>();
    detect_kernel<<<(Ec + 255) / 256, 256>>>((const long long*)eidx);
    count_kernel<<<(Ec + 255) / 256, 256>>>(eidx);
    scan_kernel<<<1, 1024>>>();
    init_cursor_kernel<<<(Nc + 255) / 256, 256>>>();
    fill_kernel<<<(Ec + 255) / 256, 256>>>(eidx);
    permute_w_kernel<<<(Bc * Ec + 255) / 256, 256>>>(edge_w);

    // Scale 0: identity copy
    copy_kernel<<<(Sc / 4 + 255) / 256, 256>>>((const float4*)x, (float4*)out);

    // Scales 1, 2: gather hops
    int hop_threads = Bc * Nc * 32;                  // one warp per (b, n)
    int hop_blocks  = (hop_threads + 255) / 256;
    hop_kernel<<<hop_blocks, 256>>>(out,            out + (size_t)Sc);
    hop_kernel<<<hop_blocks, 256>>>(out + (size_t)Sc, out + 2 * (size_t)Sc);
}

// round 5
// speedup vs baseline: 1.7941x; 1.7941x over previous
#include <cuda_runtime.h>
#include <cstdint>

// ---------------------------------------------------------------------------
// MultiScaleGraphPropagate (3, B, T, N, F) = [x, Ax, A^2 x]
// A[n, src] = mean_l edge_w[b, l, e] for e = (tgt=n, src), per (b, t) slice.
//
// CSR-by-target build, then pure-gather hops on a (B, N, T, F)-transposed
// copy of x: each edge reads one contiguous 1024B block with 2 LDG.128
// (vs 8 LDG.32 in row layout) -> 4x fewer load issues at identical bytes.
// hop1 writes final slab + transposed scratch for hop2.
// edge_index dtype (int32 vs int64) detected per-warp via ballot on the
// first 32 8-byte words (deterministic for a given input).
// ---------------------------------------------------------------------------

#define Bc 4
#define Tc 8
#define Nc 10000
#define Fc 32
#define Lc 3
#define Ec 160000
#define Sc (Bc * Tc * Nc * Fc)   // 10,240,000 floats per scale slab

// Scratch (device globals; no runtime allocation allowed)
static __device__ int   g_counts[Nc];
static __device__ int   g_offsets[Nc + 1];
static __device__ int   g_cursor[Nc];
static __device__ int   g_src[Ec];
static __device__ float g_csrw[Bc * Ec];
static __device__ float g_xt0[Sc];       // x  in (B, N, T, F)
static __device__ float g_xt1[Sc];       // Ax in (B, N, T, F)

// Warp-collective dtype probe: interpret words 0..31 of the buffer as int64;
// int64 data -> all in [0, Nc); int32 data -> word w = lo | hi<<32 with random
// hi, P(all 32 his == 0) ~ 1e-128. Deterministic per input, no global flag.
__device__ __forceinline__ bool probe_is64(const void* raw, int lane) {
    long long v = ((const long long*)raw)[lane];
    bool valid = (v >= 0) && (v < (long long)Nc);
    return __all_sync(0xffffffffu, valid);
}

// ---------------------------------------------------------------------------
__global__ void zero_kernel() {
    int i = blockIdx.x * blockDim.x + threadIdx.x;
    if (i < Nc) g_counts[i] = 0;
}

__global__ void count_kernel(const void* __restrict__ eidx) {
    int e    = blockIdx.x * blockDim.x + threadIdx.x;
    int lane = threadIdx.x & 31;
    bool is64 = probe_is64(eidx, lane);
    if (e < Ec) {
        int tgt = is64 ? (int)((const long long*)eidx)[e]
                       : ((const int*)eidx)[e];
        atomicAdd(&g_counts[tgt], 1);
    }
}

// Single-block exclusive scan; also writes g_cursor (= offsets copy).
__global__ void scan_kernel() {
    __shared__ int wsum[32];
    const int ITEMS = 10;                  // 1024*10 >= 10000
    int tid  = threadIdx.x;
    int lane = tid & 31, wid = tid >> 5;
    int base = tid * ITEMS;

    int vals[ITEMS];
    int run = 0;
#pragma unroll
    for (int i = 0; i < ITEMS; ++i) {
        int idx = base + i;
        int c = (idx < Nc) ? g_counts[idx] : 0;
        vals[i] = run;
        run += c;
    }
    int inc = run;
#pragma unroll
    for (int off = 1; off < 32; off <<= 1) {
        int v = __shfl_up_sync(0xffffffffu, inc, off);
        if (lane >= off) inc += v;
    }
    if (lane == 31) wsum[wid] = inc;
    __syncthreads();
    if (wid == 0) {
        int v = wsum[lane];
#pragma unroll
        for (int off = 1; off < 32; off <<= 1) {
            int u = __shfl_up_sync(0xffffffffu, v, off);
            if (lane >= off) v += u;
        }
        wsum[lane] = v;
    }
    __syncthreads();
    int warp_base = (wid > 0) ? wsum[wid - 1] : 0;
    int texcl = warp_base + (inc - run);
#pragma unroll
    for (int i = 0; i < ITEMS; ++i) {
        int idx = base + i;
        if (idx < Nc) {
            int o = texcl + vals[i];
            g_offsets[idx] = o;
            g_cursor[idx]  = o;
        }
    }
    if (tid == 0) g_offsets[Nc] = Ec;
}

// Fill CSR (src) and fused weight mean+permute for all 4 batches.
__global__ void fill_kernel(const void* __restrict__ eidx,
                            const float* __restrict__ edge_w) {
    int e    = blockIdx.x * blockDim.x + threadIdx.x;
    int lane = threadIdx.x & 31;
    bool is64 = probe_is64(eidx, lane);
    if (e < Ec) {
        int tgt, src;
        if (is64) {
            tgt = (int)((const long long*)eidx)[e];
            src = (int)((const long long*)eidx)[Ec + e];
        } else {
            tgt = ((const int*)eidx)[e];
            src = ((const int*)eidx)[Ec + e];
        }
        int pos = atomicAdd(&g_cursor[tgt], 1);
        g_src[pos] = src;
#pragma unroll
        for (int b = 0; b < Bc; ++b) {
            const float* ew = edge_w + b * (Lc * Ec) + e;
            float m = (ew[0] + ew[Ec] + ew[2 * Ec]) * (1.0f / 3.0f);
            g_csrw[b * Ec + pos] = m;
        }
    }
}

// Scale 0 copy + build transposed layout: xt[(b*N+n)*T*F + t*F + f] = x[b,t,n,f]
__global__ void copy_transpose_kernel(const float4* __restrict__ x,
                                      float4* __restrict__ out0) {
    int i = blockIdx.x * blockDim.x + threadIdx.x;   // over Sc/4 float4s
    if (i >= Sc / 4) return;
    float4 v = x[i];
    out0[i] = v;
    // decompose i (f4 fastest): i = ((b*Tc + t)*Nc + n)*8 + f4
    int f4 = i & 7;
    int r  = i >> 3;                 // (b*Tc + t)*Nc + n
    int n  = r % Nc;
    int bt = r / Nc;                 // b*Tc + t
    int t  = bt & 7;
    int b  = bt >> 3;
    ((float4*)g_xt0)[((b * Nc + n) * Tc + t) * 8 + f4] = v;
}

// One warp per (b, n); per edge: 2 LDG.128 over the contiguous 1024B src
// block. acc = 8 floats/lane. PASS 0: reads g_xt0, writes g_xt1 + final.
// PASS 1: reads g_xt1, writes final only.
template <int PASS>
__global__ __launch_bounds__(256) void hop_kernel(float* __restrict__ out_final) {
    int w    = (blockIdx.x * blockDim.x + threadIdx.x) >> 5;
    int lane = threadIdx.x & 31;
    if (w >= Bc * Nc) return;
    int b = w / Nc;
    int n = w - b * Nc;

    int beg = g_offsets[n];
    int end = g_offsets[n + 1];

    float4 acc0 = make_float4(0.f, 0.f, 0.f, 0.f);
    float4 acc1 = make_float4(0.f, 0.f, 0.f, 0.f);

    const float*  wrow = g_csrw + b * Ec;
    const float*  in_t = (PASS == 0) ? g_xt0 : g_xt1;
    const float4* base = (const float4*)(in_t + (unsigned)b * (Nc * Tc * Fc));

    int pos = beg;
    for (; pos + 2 <= end; pos += 2) {
        int   s0 = g_src[pos],     s1 = g_src[pos + 1];
        float w0 = wrow[pos],      w1 = wrow[pos + 1];
        const float4* p0 = base + (unsigned)s0 * 64;
        const float4* p1 = base + (unsigned)s1 * 64;
        float4 a  = __ldg(p0 + lane);
        float4 c  = __ldg(p1 + lane);
        float4 bq = __ldg(p0 + lane + 32);
        float4 d  = __ldg(p1 + lane + 32);
        acc0.x = fmaf(w0, a.x, acc0.x);  acc0.y = fmaf(w0, a.y, acc0.y);
        acc0.z = fmaf(w0, a.z, acc0.z);  acc0.w = fmaf(w0, a.w, acc0.w);
        acc1.x = fmaf(w0, bq.x, acc1.x); acc1.y = fmaf(w0, bq.y, acc1.y);
        acc1.z = fmaf(w0, bq.z, acc1.z); acc1.w = fmaf(w0, bq.w, acc1.w);
        acc0.x = fmaf(w1, c.x, acc0.x);  acc0.y = fmaf(w1, c.y, acc0.y);
        acc0.z = fmaf(w1, c.z, acc0.z);  acc0.w = fmaf(w1, c.w, acc0.w);
        acc1.x = fmaf(w1, d.x, acc1.x);  acc1.y = fmaf(w1, d.y, acc1.y);
        acc1.z = fmaf(w1, d.z, acc1.z);  acc1.w = fmaf(w1, d.w, acc1.w);
    }
    if (pos < end) {
        int   s0 = g_src[pos];
        float w0 = wrow[pos];
        const float4* p0 = base + (unsigned)s0 * 64;
        float4 a  = __ldg(p0 + lane);
        float4 bq = __ldg(p0 + lane + 32);
        acc0.x = fmaf(w0, a.x, acc0.x);  acc0.y = fmaf(w0, a.y, acc0.y);
        acc0.z = fmaf(w0, a.z, acc0.z);  acc0.w = fmaf(w0, a.w, acc0.w);
        acc1.x = fmaf(w0, bq.x, acc1.x); acc1.y = fmaf(w0, bq.y, acc1.y);
        acc1.z = fmaf(w0, bq.z, acc1.z); acc1.w = fmaf(w0, bq.w, acc1.w);
    }

    if (PASS == 0) {
        float4* q = (float4*)(g_xt1 + ((unsigned)b * Nc + (unsigned)n) * (Tc * Fc));
        q[lane]      = acc0;
        q[lane + 32] = acc1;
    }
    // final (B,T,N,F): lane l -> t = l/8, f4 = l%8; acc1 is t + 4
    {
        int t0 = lane >> 3;
        int f4 = lane & 7;
        float4* o = (float4*)(out_final
                    + ((unsigned)(b * Tc + t0) * Nc + (unsigned)n) * Fc) + f4;
        o[0] = acc0;                                   // t = t0
        o[(unsigned)4 * Nc * 8] = acc1;                // t = t0 + 4 (float4 units)
    }
}

// ---------------------------------------------------------------------------
extern "C" void kernel_launch(void* const* d_in, const int* in_sizes, int n_in,
                              void* d_out, int out_size) {
    const float* x      = (const float*)d_in[0];
    const float* edge_w = (const float*)d_in[1];
    const void*  eidx   = d_in[2];
    float*       out    = (float*)d_out;

    (void)in_sizes; (void)n_in; (void)out_size;

    zero_kernel<<<(Nc + 255) / 256, 256>>>();
    count_kernel<<<(Ec + 255) / 256, 256>>>(eidx);
    scan_kernel<<<1, 1024>>>();
    fill_kernel<<<(Ec + 255) / 256, 256>>>(eidx, edge_w);

    copy_transpose_kernel<<<(Sc / 4 + 255) / 256, 256>>>((const float4*)x,
                                                         (float4*)out);

    int hop_threads = Bc * Nc * 32;
    int hop_blocks  = (hop_threads + 255) / 256;
    hop_kernel<0><<<hop_blocks, 256>>>(out + (size_t)Sc);
    hop_kernel<1><<<hop_blocks, 256>>>(out + 2 * (size_t)Sc);
}